// round 14
// baseline (speedup 1.0000x reference)
#include <cuda_runtime.h>

#define NU 200000
#define NI 100000
#define NN 300000
#define NE 1000000
#define NE2 2000000
#define ADJ_CAP (NE2 + 3 * NN + 8)
#define SB 1024
#define GB 147                      // all scan blocks co-resident (<=148 SMs)

// Scratch (device globals — no allocation allowed)
__device__ int      g_deg[NN];
__device__ int      g_rowptr[NN + 1];
__device__ int      g_cursor[NN];
__device__ int      g_adj[ADJ_CAP];
__device__ float    g_dinv[NN];
__device__ float4   g_embA[(NN + 1) * 16];   // f32 tables, 256B rows. Row NN = zero dummy.
__device__ float4   g_embB[(NN + 1) * 16];   // P0/P2 in A, P1 in B.
__device__ int      g_part[GB];
__device__ int      g_bar;

__global__ void k_count(const int* __restrict__ uid, const int* __restrict__ iid) {
    int e = blockIdx.x * blockDim.x + threadIdx.x;
    if (e == 0) g_bar = 0;                       // reset grid barrier for this replay
    if (e < NE) {
        atomicAdd(&g_deg[uid[e]], 1);
        atomicAdd(&g_deg[NU + iid[e]], 1);
    }
}

// Fused scan over PADDED degrees + rowptr/cursor/dinv finalize + f32 P0 init.
__global__ void __launch_bounds__(SB) k_scan_fused(const float4* __restrict__ ue,
                                                   const float4* __restrict__ ie) {
    __shared__ int s[SB];
    int b = blockIdx.x, tid = threadIdx.x;
    int n0 = b * 2048 + 2 * tid;
    int v0 = (n0     < NN) ? g_deg[n0]     : 0;
    int v1 = (n0 + 1 < NN) ? g_deg[n0 + 1] : 0;
    int p0 = (v0 + 3) & ~3;                      // padded degrees (x4)
    int p1 = (v1 + 3) & ~3;
    int pair = p0 + p1;
    s[tid] = pair;
    __syncthreads();
    for (int off = 1; off < SB; off <<= 1) {
        int t = (tid >= off) ? s[tid - off] : 0;
        __syncthreads();
        s[tid] += t;
        __syncthreads();
    }
    int excl  = s[tid] - pair;
    int total = s[SB - 1];

    if (tid == 0) {
        g_part[b] = total;
        __threadfence();
        atomicAdd(&g_bar, 1);
        while (atomicAdd(&g_bar, 0) < GB) { }
    }
    __syncthreads();

    int pv = (tid < GB) ? __ldcg(&g_part[tid]) : 0;
    __syncthreads();
    s[tid] = pv;
    __syncthreads();
    for (int off = 1; off < SB; off <<= 1) {
        int t = (tid >= off) ? s[tid - off] : 0;
        __syncthreads();
        s[tid] += t;
        __syncthreads();
    }
    int boff = (b > 0) ? s[b - 1] : 0;

    int r0 = boff + excl;
    if (n0 < NN) {
        g_rowptr[n0] = r0;
        g_cursor[n0] = r0;
        g_dinv[n0]   = (v0 > 0) ? rsqrtf((float)v0) : 0.0f;
    }
    if (n0 + 1 < NN) {
        g_rowptr[n0 + 1] = r0 + p0;
        g_cursor[n0 + 1] = r0 + p0;
        g_dinv[n0 + 1]   = (v1 > 0) ? rsqrtf((float)v1) : 0.0f;
    }
    // last node's row end = global padded total (written by the thread owning the last pair)
    if (n0 + 1 == NN - 1 || n0 == NN - 1) g_rowptr[NN] = r0 + p0 + p1;
    // zero dummy row NN in both tables
    if (b == 0 && tid < 16) {
        g_embA[NN * 16 + tid] = make_float4(0.f, 0.f, 0.f, 0.f);
        g_embB[NN * 16 + tid] = make_float4(0.f, 0.f, 0.f, 0.f);
    }
    __syncthreads();

    int base = b * 2048 * 16;
    for (int t = tid; t < 2048 * 16; t += SB) {
        int elem = base + t;
        if (elem < NN * 16) {
            float4 x = (elem < NU * 16) ? __ldg(&ue[elem]) : __ldg(&ie[elem - NU * 16]);
            float di = g_dinv[elem >> 4];
            g_embA[elem] = make_float4(di * x.x, di * x.y, di * x.z, di * x.w);
        }
    }
}

__global__ void k_fill(const int* __restrict__ uid, const int* __restrict__ iid) {
    int e = blockIdx.x * blockDim.x + threadIdx.x;
    if (e < NE) {
        int u  = uid[e];
        int it = NU + iid[e];
        g_adj[atomicAdd(&g_cursor[u], 1)]  = it;
        g_adj[atomicAdd(&g_cursor[it], 1)] = u;
    }
}

// Write dummy id NN into each node's padded tail [cursor, rowptr[i+1]).
__global__ void k_pad() {
    int i = blockIdx.x * blockDim.x + threadIdx.x;
    if (i < NN) {
        int j = g_cursor[i];
        int e = g_rowptr[i + 1];
        for (; j < e; j++) g_adj[j] = NN;
    }
}

// Half-warp per node, grid-stride, shuffle-free, padded rows (no remainder):
// per 4-batch: 1 int4 adj load + 4 float4 row loads + 12 FADDs.
// MODE 0: write P_{L+1} table only (no out traffic).
// MODE 2: final — out = 0.25*(e0 + rd*(P1own + P2own) + wd*sum); fused streams
//         use ldcs/stcs (evict-first) to protect the gather table in L2.
template <int SRC /*0:A 1:B*/, int MODE>
__global__ void __launch_bounds__(256) k_gather(float4* __restrict__ out,
                                                const float4* __restrict__ ue,
                                                const float4* __restrict__ ie) {
    int lane      = threadIdx.x & 15;
    int hw_global = blockIdx.x * 16 + (threadIdx.x >> 4);
    int hw_stride = gridDim.x * 16;

    const float4* __restrict__ sv = (SRC == 0) ? g_embA : g_embB;
    float4*       __restrict__ nv = (SRC == 0) ? g_embB : g_embA;
    const int4*   __restrict__ adj4 = (const int4*)g_adj;

    for (int node = hw_global; node < NN; node += hw_stride) {
        int beg = __ldg(&g_rowptr[node]) >> 2;       // both multiples of 4
        int end = __ldg(&g_rowptr[node + 1]) >> 2;

        float ax = 0.f, ay = 0.f, az = 0.f, aw = 0.f;
        for (int j = beg; j < end; j++) {
            int4 s = __ldg(&adj4[j]);
            float4 v0 = __ldg(&sv[s.x * 16 + lane]);
            float4 v1 = __ldg(&sv[s.y * 16 + lane]);
            float4 v2 = __ldg(&sv[s.z * 16 + lane]);
            float4 v3 = __ldg(&sv[s.w * 16 + lane]);
            ax += v0.x + v1.x + v2.x + v3.x;
            ay += v0.y + v1.y + v2.y + v3.y;
            az += v0.z + v1.z + v2.z + v3.z;
            aw += v0.w + v1.w + v2.w + v3.w;
        }

        float wd  = g_dinv[node];
        int   off = node * 16 + lane;

        if (MODE == 0) {
            float w2 = wd * wd;
            nv[off] = make_float4(w2 * ax, w2 * ay, w2 * az, w2 * aw);
        } else {
            float rd = (wd > 0.f) ? (1.0f / wd) : 0.0f;
            float4 p2 = sv[off];                      // gather-source table: L2-hot
            float4 p1 = __ldcs(&g_embB[off]);         // evict-first stream
            float4 e0 = (node < NU) ? __ldcs(&ue[off]) : __ldcs(&ie[off - NU * 16]);
            __stcs(&out[off], make_float4(
                0.25f * (e0.x + rd * (p1.x + p2.x) + wd * ax),
                0.25f * (e0.y + rd * (p1.y + p2.y) + wd * ay),
                0.25f * (e0.z + rd * (p1.z + p2.z) + wd * az),
                0.25f * (e0.w + rd * (p1.w + p2.w) + wd * aw)));
        }
    }
}

extern "C" void kernel_launch(void* const* d_in, const int* in_sizes, int n_in,
                              void* d_out, int out_size) {
    const float4* ue  = (const float4*)d_in[0];   // user_emb [200000,64]
    const float4* ie  = (const float4*)d_in[1];   // item_emb [100000,64]
    const int*    uid = (const int*)d_in[2];      // user_ids [1M]
    const int*    iid = (const int*)d_in[3];      // item_ids [1M]
    float4*       out = (float4*)d_out;           // [300000,64]

    const int T = 256;

    void* p = nullptr;
    cudaGetSymbolAddress(&p, g_deg);
    cudaMemsetAsync(p, 0, NN * sizeof(int));           // memset node

    k_count     <<<(NE + T - 1) / T, T>>>(uid, iid);   // also zeroes g_bar
    k_scan_fused<<<GB, SB>>>(ue, ie);
    k_fill      <<<(NE + T - 1) / T, T>>>(uid, iid);
    k_pad       <<<(NN + T - 1) / T, T>>>();

    const int GG = 2368;                               // 148 SMs x 16 blocks
    k_gather<0, 0><<<GG, T>>>(out, ue, ie);            // P1   <-- profiled (-s 5)
    k_gather<1, 0><<<GG, T>>>(out, ue, ie);            // P2
    k_gather<0, 2><<<GG, T>>>(out, ue, ie);            // final compose
}

// round 15
// speedup vs baseline: 1.0461x; 1.0461x over previous
#include <cuda_runtime.h>

#define NU 200000
#define NI 100000
#define NN 300000
#define NE 1000000
#define NE2 2000000
#define SB 1024
#define GB 147                      // all scan blocks co-resident (<=148 SMs)

// Scratch (device globals — no allocation allowed)
__device__ int      g_deg[NN];
__device__ int      g_rowptr[NN + 1];
__device__ int      g_cursor[NN];
__device__ int      g_adj[NE2];
__device__ float    g_dinv[NN];
__device__ float4   g_embA[NN * 16];   // P_L = dinv * e_L (f32, 256B rows). P0 then P2.
__device__ float4   g_embB[NN * 16];   // P1
__device__ int      g_part[GB];
__device__ int      g_bar;

__global__ void k_count(const int* __restrict__ uid, const int* __restrict__ iid) {
    int e = blockIdx.x * blockDim.x + threadIdx.x;
    if (e == 0) g_bar = 0;
    if (e < NE) {
        atomicAdd(&g_deg[uid[e]], 1);
        atomicAdd(&g_deg[NU + iid[e]], 1);
    }
}

// Fused scan + rowptr/cursor/dinv finalize + P0 init (no out writes).
__global__ void __launch_bounds__(SB) k_scan_fused(const float4* __restrict__ ue,
                                                   const float4* __restrict__ ie) {
    __shared__ int s[SB];
    int b = blockIdx.x, tid = threadIdx.x;
    int n0 = b * 2048 + 2 * tid;
    int v0 = (n0     < NN) ? g_deg[n0]     : 0;
    int v1 = (n0 + 1 < NN) ? g_deg[n0 + 1] : 0;
    int pair = v0 + v1;
    s[tid] = pair;
    __syncthreads();
    for (int off = 1; off < SB; off <<= 1) {
        int t = (tid >= off) ? s[tid - off] : 0;
        __syncthreads();
        s[tid] += t;
        __syncthreads();
    }
    int excl  = s[tid] - pair;
    int total = s[SB - 1];

    if (tid == 0) {
        g_part[b] = total;
        __threadfence();
        atomicAdd(&g_bar, 1);
        while (atomicAdd(&g_bar, 0) < GB) { }
    }
    __syncthreads();

    int pv = (tid < GB) ? __ldcg(&g_part[tid]) : 0;
    __syncthreads();
    s[tid] = pv;
    __syncthreads();
    for (int off = 1; off < SB; off <<= 1) {
        int t = (tid >= off) ? s[tid - off] : 0;
        __syncthreads();
        s[tid] += t;
        __syncthreads();
    }
    int boff = (b > 0) ? s[b - 1] : 0;

    int r0 = boff + excl;
    if (n0 < NN) {
        g_rowptr[n0] = r0;
        g_cursor[n0] = r0;
        g_dinv[n0]   = (v0 > 0) ? rsqrtf((float)v0) : 0.0f;
    }
    if (n0 + 1 < NN) {
        g_rowptr[n0 + 1] = r0 + v0;
        g_cursor[n0 + 1] = r0 + v0;
        g_dinv[n0 + 1]   = (v1 > 0) ? rsqrtf((float)v1) : 0.0f;
    }
    if (b == 0 && tid == 0) g_rowptr[NN] = NE2;
    __syncthreads();

    int base = b * 2048 * 16;
    for (int t = tid; t < 2048 * 16; t += SB) {
        int elem = base + t;
        if (elem < NN * 16) {
            float4 x = (elem < NU * 16) ? __ldg(&ue[elem]) : __ldg(&ie[elem - NU * 16]);
            float di = g_dinv[elem >> 4];
            g_embA[elem] = make_float4(di * x.x, di * x.y, di * x.z, di * x.w);
        }
    }
}

__global__ void k_fill(const int* __restrict__ uid, const int* __restrict__ iid) {
    int e = blockIdx.x * blockDim.x + threadIdx.x;
    if (e < NE) {
        int u  = uid[e];
        int it = NU + iid[e];
        g_adj[atomicAdd(&g_cursor[u], 1)]  = it;
        g_adj[atomicAdd(&g_cursor[it], 1)] = u;
    }
}

// Half-warp (16 lanes) per node, grid-stride over [nbase, nbase+ncnt),
// shuffle-free, rows batched x4. Bipartite phase split: a launch covers only
// user nodes (random reads hit the item region, 25.6MB) or only item nodes
// (user region, 51MB) so the active gather set stays L2-resident.
// MODE 0: write P_{L+1} table only.
// MODE 2: final — out = 0.25*(e0 + rd*(P1own + P2own) + wd*sum); fused streams
//         via ldcs/stcs (evict-first) to protect the gather table in L2.
template <int SRC /*0:A 1:B*/, int MODE>
__global__ void __launch_bounds__(256) k_gather(float4* __restrict__ out,
                                                const float4* __restrict__ ue,
                                                const float4* __restrict__ ie,
                                                int nbase, int ncnt) {
    int lane      = threadIdx.x & 15;
    int hw_global = blockIdx.x * 16 + (threadIdx.x >> 4);
    int hw_stride = gridDim.x * 16;

    const float4* __restrict__ sv = (SRC == 0) ? g_embA : g_embB;
    float4*       __restrict__ nv = (SRC == 0) ? g_embB : g_embA;

    for (int ni = hw_global; ni < ncnt; ni += hw_stride) {
        int node = nbase + ni;
        int beg = __ldg(&g_rowptr[node]);
        int end = __ldg(&g_rowptr[node + 1]);

        float ax = 0.f, ay = 0.f, az = 0.f, aw = 0.f;
        int j = beg;
        for (; j + 4 <= end; j += 4) {
            int s0 = __ldg(&g_adj[j + 0]);
            int s1 = __ldg(&g_adj[j + 1]);
            int s2 = __ldg(&g_adj[j + 2]);
            int s3 = __ldg(&g_adj[j + 3]);
            float4 v0 = __ldg(&sv[s0 * 16 + lane]);
            float4 v1 = __ldg(&sv[s1 * 16 + lane]);
            float4 v2 = __ldg(&sv[s2 * 16 + lane]);
            float4 v3 = __ldg(&sv[s3 * 16 + lane]);
            ax += v0.x + v1.x + v2.x + v3.x;
            ay += v0.y + v1.y + v2.y + v3.y;
            az += v0.z + v1.z + v2.z + v3.z;
            aw += v0.w + v1.w + v2.w + v3.w;
        }
        for (; j < end; j++) {
            int s = __ldg(&g_adj[j]);
            float4 v = __ldg(&sv[s * 16 + lane]);
            ax += v.x; ay += v.y; az += v.z; aw += v.w;
        }

        float wd  = g_dinv[node];
        int   off = node * 16 + lane;

        if (MODE == 0) {
            float w2 = wd * wd;
            nv[off] = make_float4(w2 * ax, w2 * ay, w2 * az, w2 * aw);
        } else {
            float rd = (wd > 0.f) ? (1.0f / wd) : 0.0f;
            float4 p2 = sv[off];                      // gather-source table: L2-hot
            float4 p1 = __ldcs(&g_embB[off]);         // evict-first stream
            float4 e0 = (node < NU) ? __ldcs(&ue[off]) : __ldcs(&ie[off - NU * 16]);
            __stcs(&out[off], make_float4(
                0.25f * (e0.x + rd * (p1.x + p2.x) + wd * ax),
                0.25f * (e0.y + rd * (p1.y + p2.y) + wd * ay),
                0.25f * (e0.z + rd * (p1.z + p2.z) + wd * az),
                0.25f * (e0.w + rd * (p1.w + p2.w) + wd * aw)));
        }
    }
}

extern "C" void kernel_launch(void* const* d_in, const int* in_sizes, int n_in,
                              void* d_out, int out_size) {
    const float4* ue  = (const float4*)d_in[0];   // user_emb [200000,64]
    const float4* ie  = (const float4*)d_in[1];   // item_emb [100000,64]
    const int*    uid = (const int*)d_in[2];      // user_ids [1M]
    const int*    iid = (const int*)d_in[3];      // item_ids [1M]
    float4*       out = (float4*)d_out;           // [300000,64]

    const int T = 256;

    void* p = nullptr;
    cudaGetSymbolAddress(&p, g_deg);
    cudaMemsetAsync(p, 0, NN * sizeof(int));           // node 0

    k_count     <<<(NE + T - 1) / T, T>>>(uid, iid);   // node 1 (also zeroes g_bar)
    k_scan_fused<<<GB, SB>>>(ue, ie);                  // node 2
    k_fill      <<<(NE + T - 1) / T, T>>>(uid, iid);   // node 3

    const int GG = 2368;                               // 148 SMs x 16 blocks
    // Each layer: user phase (reads item region), then item phase (reads user region).
    k_gather<0, 0><<<GG, T>>>(out, ue, ie, 0,  NU);    // node 4: L1 users
    k_gather<0, 0><<<GG, T>>>(out, ue, ie, NU, NI);    // node 5: L1 items  <-- profiled
    k_gather<1, 0><<<GG, T>>>(out, ue, ie, 0,  NU);    // node 6: L2 users
    k_gather<1, 0><<<GG, T>>>(out, ue, ie, NU, NI);    // node 7: L2 items
    k_gather<0, 2><<<GG, T>>>(out, ue, ie, 0,  NU);    // node 8: L3 users + compose
    k_gather<0, 2><<<GG, T>>>(out, ue, ie, NU, NI);    // node 9: L3 items + compose
}